// round 14
// baseline (speedup 1.0000x reference)
#include <cuda_runtime.h>
#include <math.h>
#include <stdint.h>

// Problem constants (fixed by setup_inputs)
#define NB    2
#define LSEQ  2048
#define EMB   1024
#define NH    16
#define DHEAD 64
#define MROWS (NB * LSEQ)   // 4096

// Scratch (allocation-free rule: __device__ globals)
__device__ float g_Q[MROWS * EMB];
__device__ float g_K[MROWS * EMB];
__device__ float g_V[MROWS * EMB];
__device__ float g_A[MROWS * EMB];

// ---------------------------------------------------------------------------
// Helpers
// ---------------------------------------------------------------------------
__device__ __forceinline__ uint32_t f2tf(float f) {
    uint32_t u;
    asm("cvt.rna.tf32.f32 %0, %1;" : "=r"(u) : "f"(f));
    return u;
}

__device__ __forceinline__ void mma_tf32(float c[4],
    uint32_t a0, uint32_t a1, uint32_t a2, uint32_t a3,
    uint32_t b0, uint32_t b1)
{
    asm volatile(
        "mma.sync.aligned.m16n8k8.row.col.f32.tf32.tf32.f32 "
        "{%0,%1,%2,%3},{%4,%5,%6,%7},{%8,%9},{%0,%1,%2,%3};"
        : "+f"(c[0]), "+f"(c[1]), "+f"(c[2]), "+f"(c[3])
        : "r"(a0), "r"(a1), "r"(a2), "r"(a3), "r"(b0), "r"(b1));
}

// Row-hash for the permuted-tile bank swizzle.
__device__ __forceinline__ int swz(int r) { return (r & 3) ^ ((r >> 2) & 3); }

// Permuted 16-wide tile layout:
//   col c (0..15) lives at pos(c) = (c&3)*4 + (c>>2), then the 16B group index
//   is XORed with h(row) -> addr = row*16 + 4*((group ^ h)&3) + offset.
// One LDS.128 at group (lc ^ h) returns cols {lc, lc+4, lc+8, lc+12} in order:
// exactly a thread's tf32 fragment operands for TWO k=8 mma steps.

// ---------------------------------------------------------------------------
// tf32 GEMM:  C[.,1024] = A[.,1024] @ B[1024,1024]^T (+bias).
// 128x128 block tile, BK=16, 8 warps (64x32 warp tile), 256 threads.
// Operands pre-rounded (cvt.rna) in the staging store; inner loop is
// 12 LDS.128 + 32 HMMA per warp, all smem accesses bank-conflict-free.
// Register-double-buffered LDG (lag-2) + 2 smem slots.
// ---------------------------------------------------------------------------
#define GKI (EMB / 16)   // 64

__device__ __forceinline__ void gemm_body(
    const float* __restrict__ Ag, const float* __restrict__ Bg,
    const float* __restrict__ bias, float* __restrict__ C,
    int row0, int col0, int round_out)
{
    __shared__ __align__(16) float As[2][128 * 16];
    __shared__ __align__(16) float Bs[2][128 * 16];

    const int tid  = threadIdx.x;
    const int lane = tid & 31;
    const int warp = tid >> 5;
    const int wm = warp >> 2, wn = warp & 3;
    const int lr = lane >> 2, lc = lane & 3;

    float4 ra[2], rbv[2];

    auto ldg_stage = [&](int kt) {
        const int k0 = kt * 16;
        #pragma unroll
        for (int m = 0; m < 2; m++) {
            int idx = tid + 256 * m;           // 0..511
            int r = idx >> 2, j = idx & 3;     // row, 4-col chunk
            ra[m]  = *(const float4*)(Ag + (size_t)(row0 + r) * EMB + k0 + 4 * j);
            rbv[m] = *(const float4*)(Bg + (size_t)(col0 + r) * EMB + k0 + 4 * j);
        }
    };
    auto sts_stage = [&](int slot) {
        #pragma unroll
        for (int m = 0; m < 2; m++) {
            int idx = tid + 256 * m;
            int r = idx >> 2, j = idx & 3;
            int h = swz(r);
            uint32_t* pa = (uint32_t*)&As[slot][r * 16];
            uint32_t* pb = (uint32_t*)&Bs[slot][r * 16];
            const float* fa = (const float*)&ra[m];
            const float* fb = (const float*)&rbv[m];
            #pragma unroll
            for (int i = 0; i < 4; i++) {
                pa[4 * ((i ^ h) & 3) + j] = f2tf(fa[i]);
                pb[4 * ((i ^ h) & 3) + j] = f2tf(fb[i]);
            }
        }
    };

    float acc[4][4][4] = {};

    ldg_stage(0);
    sts_stage(0);
    ldg_stage(1);
    __syncthreads();

    for (int kt = 0; kt < GKI; kt++) {
        const int slot = kt & 1;
        const float* a_s = As[slot];
        const float* b_s = Bs[slot];

        uint4 afA[4], afB[4];
        #pragma unroll
        for (int mt = 0; mt < 4; mt++) {
            int rb0 = wm * 64 + mt * 16 + lr;
            int rb1 = rb0 + 8;
            afA[mt] = *(const uint4*)&a_s[rb0 * 16 + 4 * ((lc ^ swz(rb0)) & 3)];
            afB[mt] = *(const uint4*)&a_s[rb1 * 16 + 4 * ((lc ^ swz(rb1)) & 3)];
        }
        #pragma unroll
        for (int nt = 0; nt < 4; nt++) {
            int nb = wn * 32 + nt * 8 + lr;
            uint4 bf = *(const uint4*)&b_s[nb * 16 + 4 * ((lc ^ swz(nb)) & 3)];
            #pragma unroll
            for (int mt = 0; mt < 4; mt++) {
                // step0: k = 0..7 of this BK=16 tile; step1: k = 8..15
                mma_tf32(acc[mt][nt], afA[mt].x, afB[mt].x, afA[mt].y, afB[mt].y,
                         bf.x, bf.y);
                mma_tf32(acc[mt][nt], afA[mt].z, afB[mt].z, afA[mt].w, afB[mt].w,
                         bf.z, bf.w);
            }
        }

        __syncthreads();
        if (kt + 1 < GKI) sts_stage((kt + 1) & 1);
        if (kt + 2 < GKI) ldg_stage(kt + 2);
        __syncthreads();
    }

    // epilogue
    #pragma unroll
    for (int mt = 0; mt < 4; mt++) {
        int row = row0 + wm * 64 + mt * 16 + lr;
        #pragma unroll
        for (int nt = 0; nt < 4; nt++) {
            int col = col0 + wn * 32 + nt * 8 + lc * 2;
            float v0 = acc[mt][nt][0], v1 = acc[mt][nt][1];
            float v2 = acc[mt][nt][2], v3 = acc[mt][nt][3];
            if (bias) {
                float b0 = bias[col], b1 = bias[col + 1];
                v0 += b0; v1 += b1; v2 += b0; v3 += b1;
            }
            if (round_out) {
                v0 = __uint_as_float(f2tf(v0));
                v1 = __uint_as_float(f2tf(v1));
                v2 = __uint_as_float(f2tf(v2));
                v3 = __uint_as_float(f2tf(v3));
            }
            *(float2*)&C[(size_t)row * EMB + col]       = make_float2(v0, v1);
            *(float2*)&C[(size_t)(row + 8) * EMB + col] = make_float2(v2, v3);
        }
    }
}

// Fused Q/K/V projections (z selects input/weight/output), tf32-rounded out.
__global__ __launch_bounds__(256) void gemm_qkv(
    const float* __restrict__ q, const float* __restrict__ k,
    const float* __restrict__ v,
    const float* __restrict__ Wq, const float* __restrict__ Wk,
    const float* __restrict__ Wv,
    float* __restrict__ Qo, float* __restrict__ Ko, float* __restrict__ Vo)
{
    const float *A, *B;
    float* C;
    if (blockIdx.z == 0)      { A = q; B = Wq; C = Qo; }
    else if (blockIdx.z == 1) { A = k; B = Wk; C = Ko; }
    else                      { A = v; B = Wv; C = Vo; }
    gemm_body(A, B, nullptr, C, blockIdx.y * 128, blockIdx.x * 128, 1);
}

__global__ __launch_bounds__(256) void gemm_single(
    const float* __restrict__ A, const float* __restrict__ B,
    const float* __restrict__ bias, float* __restrict__ C, int round_out)
{
    gemm_body(A, B, bias, C, blockIdx.y * 128, blockIdx.x * 128, round_out);
}

// ---------------------------------------------------------------------------
// Fused flash attention, tf32 mma.sync. Block = 128 q-rows x one (batch,head).
// 8 warps x 16 q-rows. Q frags register-resident. K stored in the permuted
// 16-group layout (B-frags = LDS.128 covering 2 k-steps); V stored TRANSPOSED
// (d-major) in the same permuted layout so P@V B-frags are also LDS.128.
// K/V staged via LDG.128 regs (lag-1 tile) -> STS (no cvt needed: Q/K/V are
// pre-rounded tf32 from the projections). Softmax without max subtraction
// (exact sum-normalization; |S|<~10 so exp cannot overflow).
// ---------------------------------------------------------------------------
#define PP 68
#define ATT_NT (LSEQ / 64)   // 32

__global__ __launch_bounds__(256, 1) void attn_tf32(
    const float* __restrict__ Q, const float* __restrict__ K,
    const float* __restrict__ V, const int* __restrict__ mask,
    float* __restrict__ O)
{
    extern __shared__ __align__(16) float sm[];
    float* Ks = sm;                  // 2 slots x 64x64 (4096 floats each)
    float* Vt = sm + 2 * 4096;       // 2 slots x 64x64 (transposed, d-major)
    float* Ps = sm + 4 * 4096;       // 128 x PP

    const int tid  = threadIdx.x;
    const int lane = tid & 31;
    const int warp = tid >> 5;
    const int lr = lane >> 2;      // 0..7
    const int lc = lane & 3;       // 0..3
    const int bh = blockIdx.y;
    const int n  = bh >> 4;
    const int h  = bh & 15;
    const int q0 = blockIdx.x * 128;

    const float* Qg = Q + ((size_t)(n * LSEQ + q0)) * EMB + h * DHEAD;
    const float* Kg = K + ((size_t)n * LSEQ) * EMB + h * DHEAD;
    const float* Vg = V + ((size_t)n * LSEQ) * EMB + h * DHEAD;
    const int*   mg = mask + n * LSEQ;

    float4 rk[4], rv[4];

    auto ldg_kv = [&](int kt) {
        const int k0 = kt * 64;
        #pragma unroll
        for (int m = 0; m < 4; m++) {
            int idx = tid + 256 * m;           // 0..1023
            int rK = idx >> 4, cK = idx & 15;  // K: 2 rows/warp, coalesced
            rk[m] = *(const float4*)(Kg + (size_t)(k0 + rK) * EMB + 4 * cK);
            int rV = idx & 63, cV = idx >> 6;  // V: row-per-lane (transpose feed)
            rv[m] = *(const float4*)(Vg + (size_t)(k0 + rV) * EMB + 4 * cV);
        }
    };
    auto sts_kv = [&](int slot) {
        float* kdst = Ks + slot * 4096;
        float* vdst = Vt + slot * 4096;
        #pragma unroll
        for (int m = 0; m < 4; m++) {
            int idx = tid + 256 * m;
            // K: row rK (key), d-cols 4cK..+3; group g = cK>>2, offset j = cK&3
            int rK = idx >> 4, cK = idx & 15;
            int g = cK >> 2, j = cK & 3;
            int hh = (swz(rK) + g) & 3;
            float* base = &kdst[(g * 64 + rK) * 16];
            const float* f = (const float*)&rk[m];
            #pragma unroll
            for (int i = 0; i < 4; i++)
                base[4 * ((i ^ hh) & 3) + j] = f[i];
            // V transpose: element (k=rV, d=4cV+i) -> Vt[d-major]
            int rV = idx & 63, cV = idx >> 6;
            int gv = rV >> 4, kk = rV & 15;
            int pos = 4 * (kk & 3) + (kk >> 2);
            const float* fv = (const float*)&rv[m];
            #pragma unroll
            for (int i = 0; i < 4; i++)
                vdst[(gv * 64 + 4 * cV + i) * 16 + pos] = fv[i];
        }
    };

    // stage Q into Ps region; prefetch K/V tiles 0 (smem) and 1 (regs)
    #pragma unroll
    for (int i = 0; i < 8; i++) {
        int idx = tid + 256 * i;              // 0..2047
        int r = idx >> 4, c4 = idx & 15;
        *(float4*)&Ps[r * PP + c4 * 4] =
            *(const float4*)&Qg[(size_t)r * EMB + c4 * 4];
    }
    ldg_kv(0);
    sts_kv(0);
    ldg_kv(1);
    __syncthreads();

    // Q fragments, register resident (values are pre-rounded tf32 bits)
    uint32_t qa[8][4];
    const int rr = warp * 16 + lr;
    #pragma unroll
    for (int ks = 0; ks < 8; ks++) {
        qa[ks][0] = __float_as_uint(Ps[rr * PP + ks * 8 + lc]);
        qa[ks][1] = __float_as_uint(Ps[(rr + 8) * PP + ks * 8 + lc]);
        qa[ks][2] = __float_as_uint(Ps[rr * PP + ks * 8 + lc + 4]);
        qa[ks][3] = __float_as_uint(Ps[(rr + 8) * PP + ks * 8 + lc + 4]);
    }

    float o[8][4] = {};
    float l0 = 0.f, l1 = 0.f;     // per-lane partial row sums

    for (int kt = 0; kt < ATT_NT; kt++) {
        const float* ks_ = Ks + (kt & 1) * 4096;
        const float* vs_ = Vt + (kt & 1) * 4096;

        // S = Q @ K^T  (16 rows x 64 keys per warp); d-pairs p cover ksp 2p,2p+1
        float s[8][4] = {};
        #pragma unroll
        for (int p = 0; p < 4; p++) {
            #pragma unroll
            for (int nt = 0; nt < 8; nt++) {
                int nb = nt * 8 + lr;
                int hh = (swz(nb) + p) & 3;
                uint4 kb = *(const uint4*)&ks_[(p * 64 + nb) * 16 + 4 * ((lc ^ hh) & 3)];
                mma_tf32(s[nt], qa[2*p][0], qa[2*p][1], qa[2*p][2], qa[2*p][3],
                         kb.x, kb.y);
                mma_tf32(s[nt], qa[2*p+1][0], qa[2*p+1][1], qa[2*p+1][2], qa[2*p+1][3],
                         kb.z, kb.w);
            }
        }

        // p = mask ? exp(S/8) : 0 ; accumulate per-lane sums; stage P (tf32)
        #pragma unroll
        for (int nt = 0; nt < 8; nt++) {
            int2 mv = *(const int2*)&mg[kt * 64 + nt * 8 + lc * 2];
            float p0 = mv.x ? __expf(s[nt][0] * 0.125f) : 0.f;
            float p1 = mv.y ? __expf(s[nt][1] * 0.125f) : 0.f;
            float p2 = mv.x ? __expf(s[nt][2] * 0.125f) : 0.f;
            float p3 = mv.y ? __expf(s[nt][3] * 0.125f) : 0.f;
            l0 += p0 + p1;
            l1 += p2 + p3;
            float2 w0 = make_float2(__uint_as_float(f2tf(p0)),
                                    __uint_as_float(f2tf(p1)));
            float2 w1 = make_float2(__uint_as_float(f2tf(p2)),
                                    __uint_as_float(f2tf(p3)));
            *(float2*)&Ps[rr * PP + nt * 8 + lc * 2]       = w0;
            *(float2*)&Ps[(rr + 8) * PP + nt * 8 + lc * 2] = w1;
        }
        __syncwarp();   // P visible across warp lanes (Ps region is warp-private)

        // O += P @ V   (Vt is d-major permuted: one LDS.128 per nt per k-pair)
        #pragma unroll
        for (int p = 0; p < 4; p++) {
            uint32_t pa0[4], pa1[4];
            pa0[0] = __float_as_uint(Ps[rr * PP + (2*p) * 8 + lc]);
            pa0[1] = __float_as_uint(Ps[(rr + 8) * PP + (2*p) * 8 + lc]);
            pa0[2] = __float_as_uint(Ps[rr * PP + (2*p) * 8 + lc + 4]);
            pa0[3] = __float_as_uint(Ps[(rr + 8) * PP + (2*p) * 8 + lc + 4]);
            pa1[0] = __float_as_uint(Ps[rr * PP + (2*p+1) * 8 + lc]);
            pa1[1] = __float_as_uint(Ps[(rr + 8) * PP + (2*p+1) * 8 + lc]);
            pa1[2] = __float_as_uint(Ps[rr * PP + (2*p+1) * 8 + lc + 4]);
            pa1[3] = __float_as_uint(Ps[(rr + 8) * PP + (2*p+1) * 8 + lc + 4]);
            #pragma unroll
            for (int nt = 0; nt < 8; nt++) {
                uint4 vb = *(const uint4*)&vs_[(p * 64 + nt * 8 + lr) * 16 + 4 * lc];
                mma_tf32(o[nt], pa0[0], pa0[1], pa0[2], pa0[3], vb.x, vb.y);
                mma_tf32(o[nt], pa1[0], pa1[1], pa1[2], pa1[3], vb.z, vb.w);
            }
        }
        __syncwarp();   // P reads done before next tile's Ps writes

        __syncthreads();                       // all warps done reading K/V slots
        if (kt + 1 < ATT_NT) sts_kv((kt + 1) & 1);
        if (kt + 2 < ATT_NT) ldg_kv(kt + 2);
        __syncthreads();                       // stores visible before next compute
    }

    // epilogue: quad-reduce row sums, normalize, store
    #pragma unroll
    for (int off = 1; off < 4; off <<= 1) {
        l0 += __shfl_xor_sync(0xffffffffu, l0, off);
        l1 += __shfl_xor_sync(0xffffffffu, l1, off);
    }
    const float i0 = 1.0f / l0, i1 = 1.0f / l1;
    float* Og = O + ((size_t)(n * LSEQ + q0)) * EMB + h * DHEAD;
    #pragma unroll
    for (int nt = 0; nt < 8; nt++) {
        int col = nt * 8 + lc * 2;
        *(float2*)&Og[(size_t)rr * EMB + col] =
            make_float2(o[nt][0] * i0, o[nt][1] * i0);
        *(float2*)&Og[(size_t)(rr + 8) * EMB + col] =
            make_float2(o[nt][2] * i1, o[nt][3] * i1);
    }
}

// ---------------------------------------------------------------------------
// Launch
// ---------------------------------------------------------------------------
extern "C" void kernel_launch(void* const* d_in, const int* in_sizes, int n_in,
                              void* d_out, int out_size)
{
    const float* values = (const float*)d_in[0];
    const float* keys   = (const float*)d_in[1];
    const float* query  = (const float*)d_in[2];
    const int*   mask   = (const int*)  d_in[3];
    const float* W_q    = (const float*)d_in[4];
    const float* W_k    = (const float*)d_in[5];
    const float* W_v    = (const float*)d_in[6];
    const float* W_o    = (const float*)d_in[7];
    const float* b_o    = (const float*)d_in[8];
    float* out = (float*)d_out;

    float *Qp, *Kp, *Vp, *Ap;
    cudaGetSymbolAddress((void**)&Qp, g_Q);
    cudaGetSymbolAddress((void**)&Kp, g_K);
    cudaGetSymbolAddress((void**)&Vp, g_V);
    cudaGetSymbolAddress((void**)&Ap, g_A);

    // Q/K/V projections (outputs pre-rounded to tf32 for the attention mmas)
    gemm_qkv<<<dim3(EMB / 128, MROWS / 128, 3), 256>>>(
        query, keys, values, W_q, W_k, W_v, Qp, Kp, Vp);

    const int smem = (4 * 4096 + 128 * PP) * sizeof(float);   // 100352 B
    cudaFuncSetAttribute(attn_tf32, cudaFuncAttributeMaxDynamicSharedMemorySize, smem);
    attn_tf32<<<dim3(LSEQ / 128, NB * NH), 256, smem>>>(Qp, Kp, Vp, mask, Ap);

    // output projection (+bias), full fp32 output
    gemm_single<<<dim3(EMB / 128, MROWS / 128), 256>>>(Ap, W_o, b_o, out, 0);
}

// round 15
// speedup vs baseline: 1.1420x; 1.1420x over previous
#include <cuda_runtime.h>
#include <math.h>
#include <stdint.h>

// Problem constants (fixed by setup_inputs)
#define NB    2
#define LSEQ  2048
#define EMB   1024
#define NH    16
#define DHEAD 64
#define MROWS (NB * LSEQ)   // 4096

// Scratch (allocation-free rule: __device__ globals)
__device__ float g_Q[MROWS * EMB];     // projected Q, row-major tf32-rounded
__device__ float g_K[MROWS * EMB];     // projected K, PERMUTED row-major
__device__ float g_V[MROWS * EMB];     // projected V, TRANSPOSED+PERMUTED (per head)
__device__ float g_A[MROWS * EMB];     // attention out, PERMUTED row-major
__device__ float g_pq[MROWS * EMB];    // permuted+rounded inputs
__device__ float g_pk[MROWS * EMB];
__device__ float g_pv[MROWS * EMB];
__device__ float g_pwq[EMB * EMB];     // permuted+rounded weights
__device__ float g_pwk[EMB * EMB];
__device__ float g_pwv[EMB * EMB];
__device__ float g_pwo[EMB * EMB];

// ---------------------------------------------------------------------------
// Helpers
// ---------------------------------------------------------------------------
__device__ __forceinline__ uint32_t f2tf(float f) {
    uint32_t u;
    asm("cvt.rna.tf32.f32 %0, %1;" : "=r"(u) : "f"(f));
    return u;
}

__device__ __forceinline__ void mma_tf32(float c[4],
    uint32_t a0, uint32_t a1, uint32_t a2, uint32_t a3,
    uint32_t b0, uint32_t b1)
{
    asm volatile(
        "mma.sync.aligned.m16n8k8.row.col.f32.tf32.tf32.f32 "
        "{%0,%1,%2,%3},{%4,%5,%6,%7},{%8,%9},{%0,%1,%2,%3};"
        : "+f"(c[0]), "+f"(c[1]), "+f"(c[2]), "+f"(c[3])
        : "r"(a0), "r"(a1), "r"(a2), "r"(a3), "r"(b0), "r"(b1));
}

__device__ __forceinline__ void cp16(uint32_t smem_addr, const void* gptr) {
    asm volatile("cp.async.cg.shared.global [%0], [%1], 16;"
                 :: "r"(smem_addr), "l"(gptr));
}
__device__ __forceinline__ void cp_commit() {
    asm volatile("cp.async.commit_group;");
}
__device__ __forceinline__ void cp_wait_all() {
    asm volatile("cp.async.wait_group 0;");
}

// Row-hash for the permuted layout (depends only on row mod 16 -> consistent
// between global layout and any 16/64/128-row-aligned tile view).
__device__ __forceinline__ int swz(int r) { return (r & 3) ^ ((r >> 2) & 3); }

// Permuted row-major layout for a [R, EMB] matrix:
//   col = cc*16 + c  ->  stored at cc*16 + 4*(((c&3) ^ swz(row)) & 3) + (c>>2)
// A 16B load at group (lc ^ swz(row)) returns cols {lc, lc+4, lc+8, lc+12}:
// a thread's tf32 fragment operands for two k=8 mma steps.
__device__ __forceinline__ size_t perm_addr(int row, int col) {
    int cc = col >> 4, c = col & 15;
    return (size_t)row * EMB + cc * 16 + 4 * (((c & 3) ^ swz(row)) & 3) + (c >> 2);
}

// Transposed+permuted V layout: [n][h][kt(32)][gv(4)][d(64)][16]
//   (token t, col c) -> d-major with keys permuted pos(k16)=4*(k16&3)+(k16>>2)
__device__ __forceinline__ size_t vt_addr(int tr, int col) {
    int n = tr >> 11, t = tr & 2047;
    int h = col >> 6, d = col & 63;
    int kt = t >> 6, kk = t & 63;
    int gv = kk >> 4, k16 = kk & 15;
    int pos = 4 * (k16 & 3) + (k16 >> 2);
    return ((((size_t)(n * NH + h) * 32 + kt) * 4 + gv) * 64 + d) * 16 + pos;
}

__device__ __forceinline__ float sel4(float4 a, int s) {
    return s == 0 ? a.x : (s == 1 ? a.y : (s == 2 ? a.z : a.w));
}

// ---------------------------------------------------------------------------
// Prepass: round (cvt.rna tf32) + permute all GEMM operands into scratch.
// One thread per 16-col group. z selects the tensor.
// ---------------------------------------------------------------------------
__global__ __launch_bounds__(256) void prep(
    const float* __restrict__ q, const float* __restrict__ k,
    const float* __restrict__ v,
    const float* __restrict__ wq, const float* __restrict__ wk,
    const float* __restrict__ wv, const float* __restrict__ wo,
    float* __restrict__ pq, float* __restrict__ pk, float* __restrict__ pv,
    float* __restrict__ pwq, float* __restrict__ pwk,
    float* __restrict__ pwv, float* __restrict__ pwo)
{
    const float* in; float* out; int R;
    switch (blockIdx.z) {
        case 0: in = q;  out = pq;  R = MROWS; break;
        case 1: in = k;  out = pk;  R = MROWS; break;
        case 2: in = v;  out = pv;  R = MROWS; break;
        case 3: in = wq; out = pwq; R = EMB;   break;
        case 4: in = wk; out = pwk; R = EMB;   break;
        case 5: in = wv; out = pwv; R = EMB;   break;
        default: in = wo; out = pwo; R = EMB;  break;
    }
    int idx = blockIdx.x * 256 + threadIdx.x;
    if (idx >= R * 64) return;
    int r = idx >> 6, g = idx & 63;
    const float4* src = (const float4*)(in + (size_t)r * EMB + g * 16);
    float4 c0 = src[0], c1 = src[1], c2 = src[2], c3 = src[3];
    const int h = swz(r);
    uint4* dst = (uint4*)(out + (size_t)r * EMB + g * 16);
    #pragma unroll
    for (int qd = 0; qd < 4; qd++) {
        int s = (qd ^ h) & 3;
        uint4 w;
        w.x = f2tf(sel4(c0, s));
        w.y = f2tf(sel4(c1, s));
        w.z = f2tf(sel4(c2, s));
        w.w = f2tf(sel4(c3, s));
        dst[qd] = w;
    }
}

// ---------------------------------------------------------------------------
// tf32 GEMM on pre-permuted operands:  C = A @ B^T (+bias).
// 128x128 block tile, BK=16, 8 warps (64x32 warp tile), cp.async 2-stage.
// Inner loop: 12 LDS.128 + 32 HMMA per warp, no cvt, conflict-free.
// Epilogue modes: 0 = round+plain (Q), 1 = round+permuted (K),
//                 2 = round+transposed (V), 3 = bias+plain fp32 (output).
// ---------------------------------------------------------------------------
#define GKI (EMB / 16)   // 64

__device__ __forceinline__ void gemm_body(
    const float* __restrict__ Ag, const float* __restrict__ Bg,
    const float* __restrict__ bias, float* __restrict__ C,
    int row0, int col0, int mode)
{
    __shared__ __align__(16) float As[2][128 * 16];
    __shared__ __align__(16) float Bs[2][128 * 16];

    const int tid  = threadIdx.x;
    const int lane = tid & 31;
    const int warp = tid >> 5;
    const int wm = warp >> 2, wn = warp & 3;
    const int lr = lane >> 2, lc = lane & 3;

    const uint32_t sA[2] = { (uint32_t)__cvta_generic_to_shared(&As[0][0]),
                             (uint32_t)__cvta_generic_to_shared(&As[1][0]) };
    const uint32_t sB[2] = { (uint32_t)__cvta_generic_to_shared(&Bs[0][0]),
                             (uint32_t)__cvta_generic_to_shared(&Bs[1][0]) };

    auto load_stage = [&](int slot, int kt) {
        #pragma unroll
        for (int i = 0; i < 2; i++) {
            int idx = tid + 256 * i;          // 0..511
            int r = idx >> 2, j = idx & 3;
            cp16(sA[slot] + (uint32_t)(r * 16 + 4 * j) * 4,
                 Ag + (size_t)(row0 + r) * EMB + kt * 16 + 4 * j);
            cp16(sB[slot] + (uint32_t)(r * 16 + 4 * j) * 4,
                 Bg + (size_t)(col0 + r) * EMB + kt * 16 + 4 * j);
        }
        cp_commit();
    };

    float acc[4][4][4] = {};

    load_stage(0, 0);

    for (int kt = 0; kt < GKI; kt++) {
        cp_wait_all();
        __syncthreads();
        if (kt + 1 < GKI) load_stage((kt + 1) & 1, kt + 1);

        const float* a_s = As[kt & 1];
        const float* b_s = Bs[kt & 1];

        uint4 afA[4], afB[4];
        #pragma unroll
        for (int mt = 0; mt < 4; mt++) {
            int rb0 = wm * 64 + mt * 16 + lr;
            int rb1 = rb0 + 8;
            afA[mt] = *(const uint4*)&a_s[rb0 * 16 + 4 * ((lc ^ swz(rb0)) & 3)];
            afB[mt] = *(const uint4*)&a_s[rb1 * 16 + 4 * ((lc ^ swz(rb1)) & 3)];
        }
        #pragma unroll
        for (int nt = 0; nt < 4; nt++) {
            int nb = wn * 32 + nt * 8 + lr;
            uint4 bf = *(const uint4*)&b_s[nb * 16 + 4 * ((lc ^ swz(nb)) & 3)];
            #pragma unroll
            for (int mt = 0; mt < 4; mt++) {
                mma_tf32(acc[mt][nt], afA[mt].x, afB[mt].x, afA[mt].y, afB[mt].y,
                         bf.x, bf.y);
                mma_tf32(acc[mt][nt], afA[mt].z, afB[mt].z, afA[mt].w, afB[mt].w,
                         bf.z, bf.w);
            }
        }
    }

    // epilogue
    #pragma unroll
    for (int mt = 0; mt < 4; mt++) {
        int row = row0 + wm * 64 + mt * 16 + lr;
        #pragma unroll
        for (int nt = 0; nt < 4; nt++) {
            int col = col0 + wn * 32 + nt * 8 + lc * 2;
            float v0 = acc[mt][nt][0], v1 = acc[mt][nt][1];
            float v2 = acc[mt][nt][2], v3 = acc[mt][nt][3];
            if (mode == 3) {
                float b0 = bias[col], b1 = bias[col + 1];
                v0 += b0; v1 += b1; v2 += b0; v3 += b1;
                *(float2*)&C[(size_t)row * EMB + col]       = make_float2(v0, v1);
                *(float2*)&C[(size_t)(row + 8) * EMB + col] = make_float2(v2, v3);
            } else {
                v0 = __uint_as_float(f2tf(v0));
                v1 = __uint_as_float(f2tf(v1));
                v2 = __uint_as_float(f2tf(v2));
                v3 = __uint_as_float(f2tf(v3));
                if (mode == 0) {
                    *(float2*)&C[(size_t)row * EMB + col]       = make_float2(v0, v1);
                    *(float2*)&C[(size_t)(row + 8) * EMB + col] = make_float2(v2, v3);
                } else if (mode == 1) {
                    C[perm_addr(row, col)]         = v0;
                    C[perm_addr(row, col + 1)]     = v1;
                    C[perm_addr(row + 8, col)]     = v2;
                    C[perm_addr(row + 8, col + 1)] = v3;
                } else {
                    C[vt_addr(row, col)]           = v0;
                    C[vt_addr(row, col + 1)]       = v1;
                    C[vt_addr(row + 8, col)]       = v2;
                    C[vt_addr(row + 8, col + 1)]   = v3;
                }
            }
        }
    }
}

// Fused Q/K/V projections (z selects input/weight/output/epilogue-mode).
__global__ __launch_bounds__(256) void gemm_qkv(
    const float* __restrict__ pq, const float* __restrict__ pk,
    const float* __restrict__ pv,
    const float* __restrict__ pwq, const float* __restrict__ pwk,
    const float* __restrict__ pwv,
    float* __restrict__ Qo, float* __restrict__ Ko, float* __restrict__ Vo)
{
    const float *A, *B;
    float* C;
    int mode;
    if (blockIdx.z == 0)      { A = pq; B = pwq; C = Qo; mode = 0; }
    else if (blockIdx.z == 1) { A = pk; B = pwk; C = Ko; mode = 1; }
    else                      { A = pv; B = pwv; C = Vo; mode = 2; }
    gemm_body(A, B, nullptr, C, blockIdx.y * 128, blockIdx.x * 128, mode);
}

__global__ __launch_bounds__(256) void gemm_out(
    const float* __restrict__ A, const float* __restrict__ B,
    const float* __restrict__ bias, float* __restrict__ C)
{
    gemm_body(A, B, bias, C, blockIdx.y * 128, blockIdx.x * 128, 3);
}

// ---------------------------------------------------------------------------
// Fused flash attention. Block = 128 q-rows x one (batch,head). 8 warps x
// 16 q-rows. Q frags register-resident. K (permuted) and V (transposed+
// permuted) are cp.async-staged straight from their producer layouts; both
// S=QK^T and O=PV fragment loads are LDS.128, no cvt. Softmax without max
// subtraction (exact sum-normalization; |S|<~10 so exp cannot overflow).
// Output written permuted+rounded for the final GEMM.
// ---------------------------------------------------------------------------
#define PP 68
#define ATT_NT (LSEQ / 64)   // 32

__global__ __launch_bounds__(256, 1) void attn_tf32(
    const float* __restrict__ Q, const float* __restrict__ Kp,
    const float* __restrict__ Vt, const int* __restrict__ mask,
    float* __restrict__ O)
{
    extern __shared__ __align__(16) float sm[];
    float* Ks = sm;                  // 2 slots x 4096 (4 d-groups x 64 keys x 16)
    float* Vs = sm + 2 * 4096;       // 2 slots x 4096 (4 k-groups x 64 d x 16)
    float* Ps = sm + 4 * 4096;       // 128 x PP

    const int tid  = threadIdx.x;
    const int lane = tid & 31;
    const int warp = tid >> 5;
    const int lr = lane >> 2;      // 0..7
    const int lc = lane & 3;       // 0..3
    const int bh = blockIdx.y;
    const int n  = bh >> 4;
    const int h  = bh & 15;
    const int q0 = blockIdx.x * 128;

    const float* Qg = Q + ((size_t)(n * LSEQ + q0)) * EMB + h * DHEAD;
    const float* Kg = Kp + (size_t)n * LSEQ * EMB;            // permuted rows
    const float* Vg = Vt + (size_t)(n * NH + h) * 32 * 4096;  // [kt][gv][d][16]
    const int*   mg = mask + n * LSEQ;

    const uint32_t sK[2] = { (uint32_t)__cvta_generic_to_shared(Ks),
                             (uint32_t)__cvta_generic_to_shared(Ks + 4096) };
    const uint32_t sV[2] = { (uint32_t)__cvta_generic_to_shared(Vs),
                             (uint32_t)__cvta_generic_to_shared(Vs + 4096) };

    auto load_kv = [&](int slot, int kt) {
        const int k0 = kt * 64;
        #pragma unroll
        for (int i = 0; i < 4; i++) {
            int idx = tid + 256 * i;           // 0..1023
            // K: smem (g*64 + r)*16 + 4j  <-  permuted global row k0+r, group 4h+g
            int r = idx >> 4, g = (idx >> 2) & 3, j = idx & 3;
            cp16(sK[slot] + (uint32_t)((g * 64 + r) * 16 + 4 * j) * 4,
                 Kg + (size_t)(k0 + r) * EMB + (4 * h + g) * 16 + 4 * j);
            // V: fully linear 16KB block
            cp16(sV[slot] + (uint32_t)idx * 16,
                 Vg + (size_t)kt * 4096 + idx * 4);
        }
        cp_commit();
    };

    // stage Q into Ps region; prefetch K/V tile 0
    #pragma unroll
    for (int i = 0; i < 8; i++) {
        int idx = tid + 256 * i;              // 0..2047
        int r = idx >> 4, c4 = idx & 15;
        *(float4*)&Ps[r * PP + c4 * 4] =
            *(const float4*)&Qg[(size_t)r * EMB + c4 * 4];
    }
    load_kv(0, 0);
    __syncthreads();                          // Q visible to owner warps

    // Q fragments, register resident (values are pre-rounded tf32 bits)
    uint32_t qa[8][4];
    const int rr = warp * 16 + lr;
    #pragma unroll
    for (int ks = 0; ks < 8; ks++) {
        qa[ks][0] = __float_as_uint(Ps[rr * PP + ks * 8 + lc]);
        qa[ks][1] = __float_as_uint(Ps[(rr + 8) * PP + ks * 8 + lc]);
        qa[ks][2] = __float_as_uint(Ps[rr * PP + ks * 8 + lc + 4]);
        qa[ks][3] = __float_as_uint(Ps[(rr + 8) * PP + ks * 8 + lc + 4]);
    }

    float o[8][4] = {};
    float l0 = 0.f, l1 = 0.f;     // per-lane partial row sums

    for (int kt = 0; kt < ATT_NT; kt++) {
        cp_wait_all();
        __syncthreads();
        if (kt + 1 < ATT_NT) load_kv((kt + 1) & 1, kt + 1);

        const float* ks_ = Ks + (kt & 1) * 4096;
        const float* vs_ = Vs + (kt & 1) * 4096;

        // S = Q @ K^T  (16 rows x 64 keys per warp); d-group p covers ksp 2p,2p+1
        float s[8][4] = {};
        #pragma unroll
        for (int p = 0; p < 4; p++) {
            #pragma unroll
            for (int nt = 0; nt < 8; nt++) {
                int nb = nt * 8 + lr;
                uint4 kb = *(const uint4*)&ks_[(p * 64 + nb) * 16 +
                                               4 * ((lc ^ swz(nb)) & 3)];
                mma_tf32(s[nt], qa[2*p][0], qa[2*p][1], qa[2*p][2], qa[2*p][3],
                         kb.x, kb.y);
                mma_tf32(s[nt], qa[2*p+1][0], qa[2*p+1][1], qa[2*p+1][2],
                         qa[2*p+1][3], kb.z, kb.w);
            }
        }

        // p = mask ? exp(S/8) : 0 ; accumulate per-lane sums; stage P (tf32)
        #pragma unroll
        for (int nt = 0; nt < 8; nt++) {
            int2 mv = *(const int2*)&mg[kt * 64 + nt * 8 + lc * 2];
            float p0 = mv.x ? __expf(s[nt][0] * 0.125f) : 0.f;
            float p1 = mv.y ? __expf(s[nt][1] * 0.125f) : 0.f;
            float p2 = mv.x ? __expf(s[nt][2] * 0.125f) : 0.f;
            float p3 = mv.y ? __expf(s[nt][3] * 0.125f) : 0.f;
            l0 += p0 + p1;
            l1 += p2 + p3;
            *(float2*)&Ps[rr * PP + nt * 8 + lc * 2] =
                make_float2(__uint_as_float(f2tf(p0)), __uint_as_float(f2tf(p1)));
            *(float2*)&Ps[(rr + 8) * PP + nt * 8 + lc * 2] =
                make_float2(__uint_as_float(f2tf(p2)), __uint_as_float(f2tf(p3)));
        }
        __syncwarp();   // P visible across warp lanes (Ps region is warp-private)

        // O += P @ V   (Vs is d-major permuted: one LDS.128 per nt per k-group)
        #pragma unroll
        for (int p = 0; p < 4; p++) {
            uint32_t pa0[4], pa1[4];
            pa0[0] = __float_as_uint(Ps[rr * PP + (2*p) * 8 + lc]);
            pa0[1] = __float_as_uint(Ps[(rr + 8) * PP + (2*p) * 8 + lc]);
            pa0[2] = __float_as_uint(Ps[rr * PP + (2*p) * 8 + lc + 4]);
            pa0[3] = __float_as_uint(Ps[(rr + 8) * PP + (2*p) * 8 + lc + 4]);
            pa1[0] = __float_as_uint(Ps[rr * PP + (2*p+1) * 8 + lc]);
            pa1[1] = __float_as_uint(Ps[(rr + 8) * PP + (2*p+1) * 8 + lc]);
            pa1[2] = __float_as_uint(Ps[rr * PP + (2*p+1) * 8 + lc + 4]);
            pa1[3] = __float_as_uint(Ps[(rr + 8) * PP + (2*p+1) * 8 + lc + 4]);
            #pragma unroll
            for (int nt = 0; nt < 8; nt++) {
                uint4 vb = *(const uint4*)&vs_[(p * 64 + nt * 8 + lr) * 16 + 4 * lc];
                mma_tf32(o[nt], pa0[0], pa0[1], pa0[2], pa0[3], vb.x, vb.y);
                mma_tf32(o[nt], pa1[0], pa1[1], pa1[2], pa1[3], vb.z, vb.w);
            }
        }
        __syncwarp();   // P reads done before next tile's Ps writes
    }

    // epilogue: quad-reduce row sums, normalize, store PERMUTED+ROUNDED
    #pragma unroll
    for (int off = 1; off < 4; off <<= 1) {
        l0 += __shfl_xor_sync(0xffffffffu, l0, off);
        l1 += __shfl_xor_sync(0xffffffffu, l1, off);
    }
    const float i0 = 1.0f / l0, i1 = 1.0f / l1;
    const int grow0 = n * LSEQ + q0 + rr;
    const int grow1 = grow0 + 8;
    #pragma unroll
    for (int nt = 0; nt < 8; nt++) {
        int gcol = h * DHEAD + nt * 8 + lc * 2;
        O[perm_addr(grow0, gcol)]     = __uint_as_float(f2tf(o[nt][0] * i0));
        O[perm_addr(grow0, gcol + 1)] = __uint_as_float(f2tf(o[nt][1] * i0));
        O[perm_addr(grow1, gcol)]     = __uint_as_float(f2tf(o[nt][2] * i1));
        O[perm_addr(grow1, gcol + 1)] = __uint_as_float(f2tf(o[nt][3] * i1));
    }
}

// ---------------------------------------------------------------------------
// Launch
// ---------------------------------------------------------------------------
extern "C" void kernel_launch(void* const* d_in, const int* in_sizes, int n_in,
                              void* d_out, int out_size)
{
    const float* values = (const float*)d_in[0];
    const float* keys   = (const float*)d_in[1];
    const float* query  = (const float*)d_in[2];
    const int*   mask   = (const int*)  d_in[3];
    const float* W_q    = (const float*)d_in[4];
    const float* W_k    = (const float*)d_in[5];
    const float* W_v    = (const float*)d_in[6];
    const float* W_o    = (const float*)d_in[7];
    const float* b_o    = (const float*)d_in[8];
    float* out = (float*)d_out;

    float *Qp, *Kp, *Vp, *Ap, *pq, *pk, *pv, *pwq, *pwk, *pwv, *pwo;
    cudaGetSymbolAddress((void**)&Qp, g_Q);
    cudaGetSymbolAddress((void**)&Kp, g_K);
    cudaGetSymbolAddress((void**)&Vp, g_V);
    cudaGetSymbolAddress((void**)&Ap, g_A);
    cudaGetSymbolAddress((void**)&pq, g_pq);
    cudaGetSymbolAddress((void**)&pk, g_pk);
    cudaGetSymbolAddress((void**)&pv, g_pv);
    cudaGetSymbolAddress((void**)&pwq, g_pwq);
    cudaGetSymbolAddress((void**)&pwk, g_pwk);
    cudaGetSymbolAddress((void**)&pwv, g_pwv);
    cudaGetSymbolAddress((void**)&pwo, g_pwo);

    // 1) round+permute all GEMM operands (memory-bound prepass)
    prep<<<dim3(MROWS * 64 / 256, 1, 7), 256>>>(
        query, keys, values, W_q, W_k, W_v, W_o,
        pq, pk, pv, pwq, pwk, pwv, pwo);

    // 2) Q/K/V projections (Q plain, K permuted, V transposed - all rounded)
    gemm_qkv<<<dim3(EMB / 128, MROWS / 128, 3), 256>>>(
        pq, pk, pv, pwq, pwk, pwv, Qp, Kp, Vp);

    // 3) fused attention (writes permuted+rounded output)
    const int smem = (4 * 4096 + 128 * PP) * sizeof(float);   // 100352 B
    cudaFuncSetAttribute(attn_tf32, cudaFuncAttributeMaxDynamicSharedMemorySize, smem);
    attn_tf32<<<dim3(LSEQ / 128, NB * NH), 256, smem>>>(Qp, Kp, Vp, mask, Ap);

    // 4) output projection (+bias), plain fp32 output
    gemm_out<<<dim3(EMB / 128, MROWS / 128), 256>>>(Ap, pwo, b_o, out);
}